// round 5
// baseline (speedup 1.0000x reference)
#include <cuda_runtime.h>
#include <cstdint>

// Problem constants
#define BB 8
#define TT 128
#define DD 1024
#define VV 4096
#define RR 16
#define HH 2
#define GG (VV * RR * HH)  // 131072 rows of W
#define NBLK 1024          // 128 rows per block

typedef unsigned long long ull;

// Scratch (device globals — no allocation allowed)
__device__ float g_Spart[NBLK][128];  // per-block partial S: [block][r*8 + b]
__device__ float g_E[256];            // [b][h][r] selected-row exps (written exactly once each)
__device__ unsigned g_count = 0;      // last-block-done counter (reset by last block)

__device__ __forceinline__ void fma2(ull& d, ull a, ull b) {
    asm("fma.rn.f32x2 %0, %1, %2, %0;" : "+l"(d) : "l"(a), "l"(b));
}
__device__ __forceinline__ ull packw(float f) {
    ull r;
    asm("mov.b64 %0, {%1, %1};" : "=l"(r) : "r"(__float_as_uint(f)));
    return r;
}
__device__ __forceinline__ float lo32(ull a) { return __uint_as_float((unsigned)a); }
__device__ __forceinline__ float hi32(ull a) { return __uint_as_float((unsigned)(a >> 32)); }

// Reduce-scatter across the 8-lane c-group: on entry s[b] = lane-partial for batch b;
// on exit lane c holds the full (8-lane) sum for batch c. 7 shuffles.
__device__ __forceinline__ float rscatter8(const float s[8], int c) {
    bool b4 = (c & 4) != 0;
    float kp[4], snd[4];
#pragma unroll
    for (int i = 0; i < 4; i++) { snd[i] = b4 ? s[i] : s[i + 4]; kp[i] = b4 ? s[i + 4] : s[i]; }
#pragma unroll
    for (int i = 0; i < 4; i++) kp[i] += __shfl_xor_sync(0xffffffffu, snd[i], 4);
    bool b2 = (c & 2) != 0;
    float k2[2], s2[2];
#pragma unroll
    for (int i = 0; i < 2; i++) { s2[i] = b2 ? kp[i] : kp[i + 2]; k2[i] = b2 ? kp[i + 2] : kp[i]; }
#pragma unroll
    for (int i = 0; i < 2; i++) k2[i] += __shfl_xor_sync(0xffffffffu, s2[i], 2);
    bool b1 = (c & 1) != 0;
    float s1 = b1 ? k2[0] : k2[1];
    float k1 = b1 ? k2[1] : k2[0];
    return k1 + __shfl_xor_sync(0xffffffffu, s1, 1);
}

// Single fused kernel. Block = 256 threads (8 warps). Each warp owns 16 rows of W
// as 4 independent load streams (quads). Depth-2 software pipeline: each stream's
// load is issued TWO iterations before use -> 8 outstanding LDG.128 per thread,
// ~1000 cycles of latency tolerance.
// Lane layout: rgrp = lane>>3 picks row within a quad, c = lane&7 picks the 16B
// column slice. W loads are coalesced LDG.128 (streaming). h lives in smem,
// XOR-swizzled so the 8 c-groups hit distinct bank groups.
__global__ void __launch_bounds__(256, 2) k_main(const float* __restrict__ lhs,
                                                 const float* __restrict__ Wm,
                                                 const float* __restrict__ bias,
                                                 const void* __restrict__ pts_raw,
                                                 float* __restrict__ out) {
    __shared__ float hs[8192];   // swizzled h_last (reused as S scratch in last block)
    __shared__ float sblk[128];  // block-local S accumulation [r*8 + b]
    __shared__ int spts[16];     // points, width-detected
    __shared__ int s_last;

    const int tid = threadIdx.x;

    if (tid < 16) {
        // Detect int64 vs int32 points: values < 4096, so int64 data has all-zero hi words.
        const ull* pw = (const ull*)pts_raw;
        ull h = 0;
#pragma unroll
        for (int i = 0; i < 8; i++) h |= (pw[i] >> 32);
        bool is64 = (h == 0ULL);
        spts[tid] = is64 ? (int)((const long long*)pts_raw)[tid]
                         : ((const int*)pts_raw)[tid];
    }
    if (tid < 128) sblk[tid] = 0.f;

    // Stage h_last[b][k] = lhs[b, T-1, k] with XOR swizzle on 16B chunks.
#pragma unroll
    for (int i = 0; i < 32; i++) {
        int idx = tid + i * 256;
        int b = idx >> 10, k = idx & 1023;
        int idx16 = k * 2 + (b >> 2);
        int s = idx16 ^ ((idx16 >> 3) & 7);
        hs[s * 4 + (b & 3)] = lhs[b * (TT * DD) + (TT - 1) * DD + k];
    }
    __syncthreads();

    const int warp = tid >> 5, lane = tid & 31;
    const int rgrp = lane >> 3, c = lane & 7;
    const int rowbase = blockIdx.x * 128 + warp * 16;  // 16 rows per warp
    // Stream q (0..3) handles row rowbase + q*4 + rgrp
    const float4* P = (const float4*)Wm + (size_t)(rowbase + rgrp) * 256 + c;
    const ulonglong2* h8 = (const ulonglong2*)hs;

    // acc[q][p]: packed f32x2, pair p holds batches (2p, 2p+1) for stream q's row
    ull acc[4][4] = {};

    // Depth-2 pipeline: w0 = chunk j (in use), w1 = chunk j+1 (pending)
    float4 w0[4], w1[4];
#pragma unroll
    for (int q = 0; q < 4; q++) w0[q] = __ldcs(&P[q * 1024]);
#pragma unroll
    for (int q = 0; q < 4; q++) w1[q] = __ldcs(&P[q * 1024 + 8]);

#pragma unroll 2
    for (int j = 0; j < 32; j++) {
        int j2 = j + 2;
        if (j2 >= 32) j2 -= 32;  // wrap: last 2 iters reload chunks 0,1 (L1 hit, branchless)
        float4 nn[4];
#pragma unroll
        for (int q = 0; q < 4; q++) nn[q] = __ldcs(&P[q * 1024 + j2 * 8]);

        int k0 = j * 64 + c * 8;  // base index into the ulonglong2 view of hs
#define STEP(comp, kk)                                                        \
    do {                                                                      \
        int i16 = k0 + 2 * (kk);                                              \
        int sw = (i16 >> 3) & 7;                                              \
        ulonglong2 hA = h8[i16 ^ sw];       /* batches 0-3 */                 \
        ulonglong2 hB = h8[(i16 + 1) ^ sw]; /* batches 4-7 */                 \
        _Pragma("unroll")                                                     \
        for (int q = 0; q < 4; q++) {                                         \
            ull wd = packw(w0[q].comp);                                       \
            fma2(acc[q][0], wd, hA.x); fma2(acc[q][1], wd, hA.y);             \
            fma2(acc[q][2], wd, hB.x); fma2(acc[q][3], wd, hB.y);             \
        }                                                                     \
    } while (0)
        STEP(x, 0);
        STEP(y, 1);
        STEP(z, 2);
        STEP(w, 3);
#undef STEP
#pragma unroll
        for (int q = 0; q < 4; q++) { w0[q] = w1[q]; w1[q] = nn[q]; }
    }

    // Per-stream: unpack, reduce-scatter so lane c ends with batch c's full sum.
    float tot[4];
#pragma unroll
    for (int q = 0; q < 4; q++) {
        float s[8];
#pragma unroll
        for (int p = 0; p < 4; p++) {
            s[2 * p] = lo32(acc[q][p]);
            s[2 * p + 1] = hi32(acc[q][p]);
        }
        tot[q] = rscatter8(s, c);
    }

    // Emit: every lane handles batch b=c for its 4 rows. Conflict-free smem atomics.
#pragma unroll
    for (int q = 0; q < 4; q++) {
        int g = rowbase + q * 4 + rgrp;
        float ev = expf(tot[q] + __ldg(&bias[g]));
        int r = g & (RR - 1);
        atomicAdd(&sblk[r * 8 + c], ev);
        int hidx = g >> 16;
        int v = (g >> 4) & (VV - 1);
        if (v == spts[c * 2 + hidx]) g_E[c * 32 + hidx * 16 + r] = ev;
    }

    __syncthreads();
    if (tid < 128) g_Spart[blockIdx.x][tid] = sblk[tid];
    __threadfence();
    __syncthreads();
    if (tid == 0) {
        unsigned o = atomicAdd(&g_count, 1);
        s_last = (o == (unsigned)(gridDim.x - 1));
    }
    __syncthreads();

    if (s_last) {
        // Final reduction: thread = (h, b, r); blocks [h*512, h*512+512) cover head h.
        int r = tid & 15, b = (tid >> 4) & 7, h = tid >> 7;
        float a = 0.f;
#pragma unroll 8
        for (int i = 0; i < NBLK / 2; i++) a += g_Spart[h * (NBLK / 2) + i][r * 8 + b];
        hs[b * 32 + h * 16 + r] = a;  // reuse hs as S[b][h][r]
        __syncthreads();
        if (tid < 8) {
            float n = 0.f, p = 0.f;
#pragma unroll
            for (int rr = 0; rr < 16; rr++) {
                n += hs[tid * 32 + rr] * hs[tid * 32 + 16 + rr];
                p += g_E[tid * 32 + rr] * g_E[tid * 32 + 16 + rr];
            }
            out[tid] = p;       // p_eval
            out[8 + tid] = n;   // norm_const
        }
        if (tid == 0) g_count = 0;  // reset for next graph replay
    }
}

extern "C" void kernel_launch(void* const* d_in, const int* in_sizes, int n_in,
                              void* d_out, int out_size) {
    // Identify inputs by element count (robust to ordering)
    const float* lhs = nullptr;
    const float* Wm = nullptr;
    const float* bias = nullptr;
    const void* pts = nullptr;
    for (int i = 0; i < n_in; i++) {
        int sz = in_sizes[i];
        if (sz == GG * DD) Wm = (const float*)d_in[i];
        else if (sz == BB * TT * DD) lhs = (const float*)d_in[i];
        else if (sz == GG) bias = (const float*)d_in[i];
        else if (sz == BB * HH) pts = d_in[i];
    }
    if (!lhs) lhs = (const float*)d_in[0];
    if (!Wm) Wm = (const float*)d_in[1];
    if (!bias) bias = (const float*)d_in[2];
    if (!pts) pts = d_in[3];

    k_main<<<NBLK, 256>>>(lhs, Wm, bias, pts, (float*)d_out);
}

// round 7
// speedup vs baseline: 1.2403x; 1.2403x over previous
#include <cuda_runtime.h>
#include <cstdint>

// Problem constants
#define BB 8
#define TT 128
#define DD 1024
#define VV 4096
#define RR 16
#define HH 2
#define GG (VV * RR * HH)  // 131072 rows of W
#define NBLK 1024          // 128 rows per block
#define NTILE 32           // 32 k-tiles of 32 columns each

// Dynamic smem layout (bytes)
#define SM_W 0                       // 4 stages x 16KB W tiles
#define SM_HS 65536                  // 8192 floats: swizzled h_last
#define SM_SBLK (SM_HS + 32768)      // 128 floats: block-local S
#define SM_SPTS (SM_SBLK + 512)      // 16 ints: points
#define SM_LAST (SM_SPTS + 64)       // 1 int: last-block flag
#define SMEM_TOTAL (SM_LAST + 64)

typedef unsigned long long ull;

// Scratch (device globals — no allocation allowed)
__device__ float g_S[256];       // [h][r*8+b] sums of exp (reset by last block each run)
__device__ float g_E[256];       // [b][h][r] selected-row exps (overwritten every run)
__device__ unsigned g_count = 0; // last-block-done counter (reset by last block)

__device__ __forceinline__ void fma2(ull& d, ull a, ull b) {
    asm("fma.rn.f32x2 %0, %1, %2, %0;" : "+l"(d) : "l"(a), "l"(b));
}
__device__ __forceinline__ ull packw(float f) {
    ull r;
    asm("mov.b64 %0, {%1, %1};" : "=l"(r) : "r"(__float_as_uint(f)));
    return r;
}
__device__ __forceinline__ float lo32(ull a) { return __uint_as_float((unsigned)a); }
__device__ __forceinline__ float hi32(ull a) { return __uint_as_float((unsigned)(a >> 32)); }

__device__ __forceinline__ void cp16(uint32_t dst, const float* src) {
    asm volatile("cp.async.cg.shared.global [%0], [%1], 16;" :: "r"(dst), "l"(src) : "memory");
}
__device__ __forceinline__ void cp_commit() {
    asm volatile("cp.async.commit_group;" ::: "memory");
}
__device__ __forceinline__ void cp_wait2() {
    asm volatile("cp.async.wait_group 2;" ::: "memory");
}

// Reduce-scatter across the 8-lane c-group: on entry s[b] = lane-partial for batch b;
// on exit lane c holds the full (8-lane) sum for batch c. 7 shuffles.
__device__ __forceinline__ float rscatter8(const float s[8], int c) {
    bool b4 = (c & 4) != 0;
    float kp[4], snd[4];
#pragma unroll
    for (int i = 0; i < 4; i++) { snd[i] = b4 ? s[i] : s[i + 4]; kp[i] = b4 ? s[i + 4] : s[i]; }
#pragma unroll
    for (int i = 0; i < 4; i++) kp[i] += __shfl_xor_sync(0xffffffffu, snd[i], 4);
    bool b2 = (c & 2) != 0;
    float k2[2], s2[2];
#pragma unroll
    for (int i = 0; i < 2; i++) { s2[i] = b2 ? kp[i] : kp[i + 2]; k2[i] = b2 ? kp[i + 2] : kp[i]; }
#pragma unroll
    for (int i = 0; i < 2; i++) k2[i] += __shfl_xor_sync(0xffffffffu, s2[i], 2);
    bool b1 = (c & 1) != 0;
    float s1 = b1 ? k2[0] : k2[1];
    float k1 = b1 ? k2[1] : k2[0];
    return k1 + __shfl_xor_sync(0xffffffffu, s1, 1);
}

// Block = 256 threads (8 warps), 128 rows of W per block.
// W flows through a 4-stage cp.async smem ring (16KB tiles, 3 groups in flight ->
// 48KB/CTA outstanding, register-free). Each thread's cp.async chunks are exactly
// the chunks it later reads (self-consumer) -> wait_group alone synchronizes,
// no barriers in the mainloop. All smem access lane-contiguous -> conflict-free.
// h lives in smem, XOR-swizzled so the 8 c-groups broadcast (1 wavefront/LDS).
__global__ void __launch_bounds__(256, 2) k_main(const float* __restrict__ lhs,
                                                 const float* __restrict__ Wm,
                                                 const float* __restrict__ bias,
                                                 const void* __restrict__ pts_raw,
                                                 float* __restrict__ out) {
    extern __shared__ char smem[];
    float* hs = (float*)(smem + SM_HS);
    float* sblk = (float*)(smem + SM_SBLK);
    int* spts = (int*)(smem + SM_SPTS);
    int* s_last = (int*)(smem + SM_LAST);

    const int tid = threadIdx.x;
    const int warp = tid >> 5, lane = tid & 31;
    const int rgrp = lane >> 3, c = lane & 7;
    const int rowbase = blockIdx.x * 128 + warp * 16;  // 16 rows per warp (4 quads)

    const uint32_t smem_u32 = (uint32_t)__cvta_generic_to_shared(smem);
    // This thread's private landing slot: + stage*16384 + q*512
    const uint32_t wdst = smem_u32 + SM_W + warp * 2048 + lane * 16;
    // This thread's global source: + q*4096 floats (4 rows) + t*32 floats (k-tile)
    const float* gsrc = Wm + (size_t)(rowbase + rgrp) * 1024 + c * 4;

    // Prologue: issue tiles 0..2 immediately (overlaps with h staging below)
#pragma unroll
    for (int t = 0; t < 3; t++) {
        uint32_t d = wdst + t * 16384;
#pragma unroll
        for (int q = 0; q < 4; q++) cp16(d + q * 512, gsrc + q * 4096 + t * 32);
        cp_commit();
    }

    if (tid < 16) {
        // Detect int64 vs int32 points: values < 4096, so int64 data has all-zero hi words.
        const ull* pw = (const ull*)pts_raw;
        ull h = 0;
#pragma unroll
        for (int i = 0; i < 8; i++) h |= (pw[i] >> 32);
        bool is64 = (h == 0ULL);
        spts[tid] = is64 ? (int)((const long long*)pts_raw)[tid]
                         : ((const int*)pts_raw)[tid];
    }
    if (tid < 128) sblk[tid] = 0.f;

    // Stage h_last[b][k] = lhs[b, T-1, k] with XOR swizzle on 16B chunks.
#pragma unroll
    for (int i = 0; i < 32; i++) {
        int idx = tid + i * 256;
        int b = idx >> 10, k = idx & 1023;
        int idx16 = k * 2 + (b >> 2);
        int s = idx16 ^ ((idx16 >> 3) & 7);
        hs[s * 4 + (b & 3)] = lhs[b * (TT * DD) + (TT - 1) * DD + k];
    }
    __syncthreads();

    const ulonglong2* h8 = (const ulonglong2*)hs;

    // acc[q][p]: packed f32x2, pair p holds batches (2p, 2p+1) for quad q's row
    ull acc[4][4] = {};

    for (int t = 0; t < NTILE; t++) {
        cp_wait2();  // tile t's group (and all earlier) complete
        if (t + 3 < NTILE) {
            uint32_t d = wdst + ((t + 3) & 3) * 16384;
#pragma unroll
            for (int q = 0; q < 4; q++) cp16(d + q * 512, gsrc + q * 4096 + (t + 3) * 32);
        }
        cp_commit();  // always commit (possibly empty) to keep group count uniform

        uint32_t s = wdst + (t & 3) * 16384;
        float4 w[4];
#pragma unroll
        for (int q = 0; q < 4; q++) {
            asm volatile("ld.shared.v4.f32 {%0,%1,%2,%3}, [%4];"
                         : "=f"(w[q].x), "=f"(w[q].y), "=f"(w[q].z), "=f"(w[q].w)
                         : "r"(s + q * 512));
        }

        int k0 = t * 64 + c * 8;  // base index into the ulonglong2 view of hs
#define STEP(comp, kk)                                                        \
    do {                                                                      \
        int i16 = k0 + 2 * (kk);                                              \
        int sw = (i16 >> 3) & 7;                                              \
        ulonglong2 hA = h8[i16 ^ sw];       /* batches 0-3 */                 \
        ulonglong2 hB = h8[(i16 + 1) ^ sw]; /* batches 4-7 */                 \
        _Pragma("unroll")                                                     \
        for (int q = 0; q < 4; q++) {                                         \
            ull wd = packw(w[q].comp);                                        \
            fma2(acc[q][0], wd, hA.x); fma2(acc[q][1], wd, hA.y);             \
            fma2(acc[q][2], wd, hB.x); fma2(acc[q][3], wd, hB.y);             \
        }                                                                     \
    } while (0)
        STEP(x, 0);
        STEP(y, 1);
        STEP(z, 2);
        STEP(w, 3);
#undef STEP
    }

    // Per-quad: unpack, reduce-scatter so lane c ends with batch c's full sum.
    float tot[4];
#pragma unroll
    for (int q = 0; q < 4; q++) {
        float s[8];
#pragma unroll
        for (int p = 0; p < 4; p++) {
            s[2 * p] = lo32(acc[q][p]);
            s[2 * p + 1] = hi32(acc[q][p]);
        }
        tot[q] = rscatter8(s, c);
    }

    // Emit: every lane handles batch b=c for its 4 rows. Conflict-free smem atomics.
#pragma unroll
    for (int q = 0; q < 4; q++) {
        int g = rowbase + q * 4 + rgrp;
        float ev = expf(tot[q] + __ldg(&bias[g]));
        int r = g & (RR - 1);
        atomicAdd(&sblk[r * 8 + c], ev);
        int hidx = g >> 16;
        int v = (g >> 4) & (VV - 1);
        if (v == spts[c * 2 + hidx]) g_E[c * 32 + hidx * 16 + r] = ev;
    }

    __syncthreads();
    // One global red per slot per block (128 REDG, spread over time across blocks).
    // All rows in a block share one h (128-row blocks, h boundary at 65536).
    int hblk = rowbase >> 16;
    if (tid < 128) atomicAdd(&g_S[hblk * 128 + tid], sblk[tid]);
    __threadfence();
    __syncthreads();
    if (tid == 0) {
        unsigned o = atomicAdd(&g_count, 1);
        *s_last = (o == (unsigned)(NBLK - 1));
    }
    __syncthreads();

    if (*s_last) {
        __threadfence();  // acquire: make all blocks' g_S reds visible
        if (tid < 8) {
            float n = 0.f, p = 0.f;
#pragma unroll
            for (int rr = 0; rr < 16; rr++) {
                // S[b][h][r] = g_S[h*128 + r*8 + b]
                n += g_S[rr * 8 + tid] * g_S[128 + rr * 8 + tid];
                p += g_E[tid * 32 + rr] * g_E[tid * 32 + 16 + rr];
            }
            out[tid] = p;       // p_eval
            out[8 + tid] = n;   // norm_const
        }
        __syncthreads();  // outputs written before scratch reset
        if (tid < 256) g_S[tid] = 0.f;  // reset for next graph replay
        if (tid == 0) g_count = 0;
    }
}

extern "C" void kernel_launch(void* const* d_in, const int* in_sizes, int n_in,
                              void* d_out, int out_size) {
    // Identify inputs by element count (robust to ordering)
    const float* lhs = nullptr;
    const float* Wm = nullptr;
    const float* bias = nullptr;
    const void* pts = nullptr;
    for (int i = 0; i < n_in; i++) {
        int sz = in_sizes[i];
        if (sz == GG * DD) Wm = (const float*)d_in[i];
        else if (sz == BB * TT * DD) lhs = (const float*)d_in[i];
        else if (sz == GG) bias = (const float*)d_in[i];
        else if (sz == BB * HH) pts = d_in[i];
    }
    if (!lhs) lhs = (const float*)d_in[0];
    if (!Wm) Wm = (const float*)d_in[1];
    if (!bias) bias = (const float*)d_in[2];
    if (!pts) pts = d_in[3];

    cudaFuncSetAttribute(k_main, cudaFuncAttributeMaxDynamicSharedMemorySize, SMEM_TOTAL);
    k_main<<<NBLK, 256, SMEM_TOTAL>>>(lhs, Wm, bias, pts, (float*)d_out);
}

// round 8
// speedup vs baseline: 1.2698x; 1.0238x over previous
#include <cuda_runtime.h>
#include <cstdint>

// Problem constants
#define BB 8
#define TT 128
#define DD 1024
#define VV 4096
#define RR 16
#define HH 2
#define GG (VV * RR * HH)  // 131072 rows of W
#define NU 2048            // work units of 64 rows
#define NCTA 296           // persistent CTAs, 2 per SM
#define STAGES 6           // cp.async ring stages
#define STAGE_BYTES 8192   // 64 rows x 32 cols x 4B per stage

// Dynamic smem layout (bytes)
#define SM_W 0
#define SM_HS (STAGES * STAGE_BYTES)   // 49152: 8192 floats swizzled h_last
#define SM_SBLK (SM_HS + 32768)        // 256 floats: CTA-local S [h][r*8+b]
#define SM_SPTS (SM_SBLK + 1024)       // 16 ints: points
#define SM_MISC (SM_SPTS + 64)         // tickets + last flag
#define SMEM_TOTAL (SM_MISC + 64)

typedef unsigned long long ull;

// Scratch (device globals — no allocation allowed)
__device__ float g_S[256];       // [h][r*8+b] sums of exp (reset by last CTA each run)
__device__ float g_E[256];       // [b][h][r] selected-row exps (all slots rewritten every run)
__device__ unsigned g_tick = 0;  // work ticket counter (reset by last CTA)
__device__ unsigned g_fin = 0;   // finished-CTA counter (reset by last CTA)

__device__ __forceinline__ void fma2(ull& d, ull a, ull b) {
    asm("fma.rn.f32x2 %0, %1, %2, %0;" : "+l"(d) : "l"(a), "l"(b));
}
__device__ __forceinline__ ull packw(float f) {
    ull r;
    asm("mov.b64 %0, {%1, %1};" : "=l"(r) : "r"(__float_as_uint(f)));
    return r;
}
__device__ __forceinline__ float lo32(ull a) { return __uint_as_float((unsigned)a); }
__device__ __forceinline__ float hi32(ull a) { return __uint_as_float((unsigned)(a >> 32)); }

__device__ __forceinline__ void cp16(uint32_t dst, const float* src) {
    asm volatile("cp.async.cg.shared.global [%0], [%1], 16;" :: "r"(dst), "l"(src) : "memory");
}
__device__ __forceinline__ void cp_commit() {
    asm volatile("cp.async.commit_group;" ::: "memory");
}
__device__ __forceinline__ void cp_wait4() {
    asm volatile("cp.async.wait_group 4;" ::: "memory");
}
__device__ __forceinline__ void cp_waitall() {
    asm volatile("cp.async.wait_all;" ::: "memory");
}

// Reduce-scatter across the 8-lane c-group: on entry s[b] = lane-partial for batch b;
// on exit lane c holds the full (8-lane) sum for batch c. 7 shuffles.
__device__ __forceinline__ float rscatter8(const float s[8], int c) {
    bool b4 = (c & 4) != 0;
    float kp[4], snd[4];
#pragma unroll
    for (int i = 0; i < 4; i++) { snd[i] = b4 ? s[i] : s[i + 4]; kp[i] = b4 ? s[i + 4] : s[i]; }
#pragma unroll
    for (int i = 0; i < 4; i++) kp[i] += __shfl_xor_sync(0xffffffffu, snd[i], 4);
    bool b2 = (c & 2) != 0;
    float k2[2], s2[2];
#pragma unroll
    for (int i = 0; i < 2; i++) { s2[i] = b2 ? kp[i] : kp[i + 2]; k2[i] = b2 ? kp[i + 2] : kp[i]; }
#pragma unroll
    for (int i = 0; i < 2; i++) k2[i] += __shfl_xor_sync(0xffffffffu, s2[i], 2);
    bool b1 = (c & 1) != 0;
    float s1 = b1 ? k2[0] : k2[1];
    float k1 = b1 ? k2[1] : k2[0];
    return k1 + __shfl_xor_sync(0xffffffffu, s1, 1);
}

// Persistent kernel: 296 CTAs x 256 threads (2 CTAs/SM). Each CTA pulls 64-row
// units via a global ticket. W flows through a 6-stage cp.async smem ring (8KB
// tiles, 5 groups = 40KB/CTA in flight, register-free). Each thread's cp.async
// chunks are exactly the chunks it later reads (self-consumer) -> wait_group
// alone synchronizes the ring; the only barriers are at unit boundaries, and
// the ring runs 5 tiles ahead so they never starve DRAM. The next unit's
// ticket is taken one unit early so prefetch crosses unit boundaries.
// h lives in smem, XOR-swizzled so the 8 c-groups broadcast (1 wavefront/LDS);
// the swizzle term for this layout reduces to a constant XOR with c.
__global__ void __launch_bounds__(256, 2) k_main(const float* __restrict__ lhs,
                                                 const float* __restrict__ Wm,
                                                 const float* __restrict__ bias,
                                                 const void* __restrict__ pts_raw,
                                                 float* __restrict__ out) {
    extern __shared__ char smem[];
    float* hs = (float*)(smem + SM_HS);
    float* sblk = (float*)(smem + SM_SBLK);
    int* spts = (int*)(smem + SM_SPTS);
    int* misc = (int*)(smem + SM_MISC);  // [0]=cur ticket, [1]=next ticket, [2]=last flag

    const int tid = threadIdx.x;
    const int warp = tid >> 5, lane = tid & 31;
    const int rgrp = lane >> 3, c = lane & 7;

    const uint32_t smem_u32 = (uint32_t)__cvta_generic_to_shared(smem);
    // This thread's private ring slot: + stage*8192 + q*512
    const uint32_t wbase = smem_u32 + SM_W + warp * 1024 + lane * 16;

    if (tid < 16) {
        // Detect int64 vs int32 points: values < 4096, so int64 data has all-zero hi words.
        const ull* pw = (const ull*)pts_raw;
        ull h = 0;
#pragma unroll
        for (int i = 0; i < 8; i++) h |= (pw[i] >> 32);
        bool is64 = (h == 0ULL);
        spts[tid] = is64 ? (int)((const long long*)pts_raw)[tid]
                         : ((const int*)pts_raw)[tid];
    }
    sblk[tid] = 0.f;

    // Stage h_last[b][k] = lhs[b, T-1, k] with XOR swizzle on 16B chunks.
#pragma unroll
    for (int i = 0; i < 32; i++) {
        int idx = tid + i * 256;
        int b = idx >> 10, k = idx & 1023;
        int idx16 = k * 2 + (b >> 2);
        int s = idx16 ^ ((idx16 >> 3) & 7);
        hs[s * 4 + (b & 3)] = lhs[b * (TT * DD) + (TT - 1) * DD + k];
    }

    if (tid == 0) {
        misc[0] = (int)atomicAdd(&g_tick, 1u);
        misc[1] = (int)atomicAdd(&g_tick, 1u);
    }
    __syncthreads();
    int cur = misc[0];
    int nxt = misc[1];

    const ulonglong2* h8 = (const ulonglong2*)hs;
    int swrite = 5, sread = 0;

    // Prologue: issue tiles 0..4 of cur (stages 0..4)
    if (cur < NU) {
        const float* g0 = Wm + (size_t)(cur * 64 + warp * 8 + rgrp) * 1024 + c * 4;
#pragma unroll
        for (int t = 0; t < 5; t++) {
            uint32_t d = wbase + t * STAGE_BYTES;
            cp16(d, g0 + t * 32);
            cp16(d + 512, g0 + 4096 + t * 32);  // q=1: row +4
            cp_commit();
        }
    } else {
#pragma unroll
        for (int t = 0; t < 5; t++) cp_commit();
    }

    while (cur < NU) {
        const float* gc = Wm + (size_t)(cur * 64 + warp * 8 + rgrp) * 1024 + c * 4;
        const float* gn = (nxt < NU)
                              ? Wm + (size_t)(nxt * 64 + warp * 8 + rgrp) * 1024 + c * 4
                              : (const float*)0;

        ull acc[2][4] = {};

        for (int t = 0; t < 32; t++) {
            cp_wait4();  // tile t complete
            {
                int ft = t + 5;
                uint32_t d = wbase + swrite * STAGE_BYTES;
                if (ft < 32) {
                    cp16(d, gc + ft * 32);
                    cp16(d + 512, gc + 4096 + ft * 32);
                } else if (gn) {
                    int f2 = ft - 32;
                    cp16(d, gn + f2 * 32);
                    cp16(d + 512, gn + 4096 + f2 * 32);
                }
                cp_commit();  // always commit to keep group accounting uniform
                swrite++; if (swrite == STAGES) swrite = 0;
            }

            uint32_t s = wbase + sread * STAGE_BYTES;
            sread++; if (sread == STAGES) sread = 0;
            float4 w[2];
            asm volatile("ld.shared.v4.f32 {%0,%1,%2,%3}, [%4];"
                         : "=f"(w[0].x), "=f"(w[0].y), "=f"(w[0].z), "=f"(w[0].w)
                         : "r"(s));
            asm volatile("ld.shared.v4.f32 {%0,%1,%2,%3}, [%4];"
                         : "=f"(w[1].x), "=f"(w[1].y), "=f"(w[1].z), "=f"(w[1].w)
                         : "r"(s + 512));

            // h addresses: base has low-3 bits clear; swizzle reduces to XOR with c.
            const ulonglong2* hb = h8 + t * 64 + c * 8;
#define STEP(comp, kk)                                                        \
    do {                                                                      \
        ulonglong2 hA = hb[(2 * (kk)) ^ c];     /* batches 0-3 */             \
        ulonglong2 hB = hb[(2 * (kk) + 1) ^ c]; /* batches 4-7 */             \
        ull wd0 = packw(w[0].comp);                                           \
        fma2(acc[0][0], wd0, hA.x); fma2(acc[0][1], wd0, hA.y);               \
        fma2(acc[0][2], wd0, hB.x); fma2(acc[0][3], wd0, hB.y);               \
        ull wd1 = packw(w[1].comp);                                           \
        fma2(acc[1][0], wd1, hA.x); fma2(acc[1][1], wd1, hA.y);               \
        fma2(acc[1][2], wd1, hB.x); fma2(acc[1][3], wd1, hB.y);               \
    } while (0)
            STEP(x, 0);
            STEP(y, 1);
            STEP(z, 2);
            STEP(w, 3);
#undef STEP
        }

        // Unit epilogue: reduce-scatter (lane c ends with batch c), exp, accumulate.
        int hidx = cur >> 10;  // (cur*64) >> 16
#pragma unroll
        for (int q = 0; q < 2; q++) {
            float s[8];
#pragma unroll
            for (int p = 0; p < 4; p++) {
                s[2 * p] = lo32(acc[q][p]);
                s[2 * p + 1] = hi32(acc[q][p]);
            }
            float tot = rscatter8(s, c);
            int g = cur * 64 + warp * 8 + q * 4 + rgrp;
            float ev = expf(tot + __ldg(&bias[g]));
            int r = g & (RR - 1);
            atomicAdd(&sblk[hidx * 128 + r * 8 + c], ev);
            int v = (g >> 4) & (VV - 1);
            if (v == spts[c * 2 + hidx]) g_E[c * 32 + hidx * 16 + r] = ev;
        }

        // Advance: cur <- nxt (its tiles 0..4 are already in the ring), grab a new nxt.
        cur = nxt;
        if (cur < NU) {
            if (tid == 0) misc[1] = (int)atomicAdd(&g_tick, 1u);
            __syncthreads();
            nxt = misc[1];
        }
    }

    cp_waitall();    // drain ring before CTA teardown
    __syncthreads(); // all unit epilogues' sblk atomics done
    atomicAdd(&g_S[tid], sblk[tid]);  // tid in [0,256): one red per slot per CTA
    __threadfence();
    __syncthreads();
    if (tid == 0) {
        unsigned o = atomicAdd(&g_fin, 1u);
        misc[2] = (o == (unsigned)(NCTA - 1));
    }
    __syncthreads();

    if (misc[2]) {
        __threadfence();  // acquire: all CTAs' g_S reds visible
        if (tid < 8) {
            float n = 0.f, p = 0.f;
#pragma unroll
            for (int rr = 0; rr < 16; rr++) {
                n += g_S[rr * 8 + tid] * g_S[128 + rr * 8 + tid];
                p += g_E[tid * 32 + rr] * g_E[tid * 32 + 16 + rr];
            }
            out[tid] = p;       // p_eval
            out[8 + tid] = n;   // norm_const
        }
        __syncthreads();  // outputs written before scratch reset
        g_S[tid] = 0.f;   // reset for next graph replay
        if (tid == 0) { g_tick = 0; g_fin = 0; }
    }
}

extern "C" void kernel_launch(void* const* d_in, const int* in_sizes, int n_in,
                              void* d_out, int out_size) {
    // Identify inputs by element count (robust to ordering)
    const float* lhs = nullptr;
    const float* Wm = nullptr;
    const float* bias = nullptr;
    const void* pts = nullptr;
    for (int i = 0; i < n_in; i++) {
        int sz = in_sizes[i];
        if (sz == GG * DD) Wm = (const float*)d_in[i];
        else if (sz == BB * TT * DD) lhs = (const float*)d_in[i];
        else if (sz == GG) bias = (const float*)d_in[i];
        else if (sz == BB * HH) pts = d_in[i];
    }
    if (!lhs) lhs = (const float*)d_in[0];
    if (!Wm) Wm = (const float*)d_in[1];
    if (!bias) bias = (const float*)d_in[2];
    if (!pts) pts = d_in[3];

    cudaFuncSetAttribute(k_main, cudaFuncAttributeMaxDynamicSharedMemorySize, SMEM_TOTAL);
    k_main<<<NCTA, 256, SMEM_TOTAL>>>(lhs, Wm, bias, pts, (float*)d_out);
}

// round 11
// speedup vs baseline: 1.2899x; 1.0158x over previous
#include <cuda_runtime.h>
#include <cstdint>

// Problem constants
#define BB 8
#define TT 128
#define DD 1024
#define VV 4096
#define RR 16
#define HH 2
#define GG (VV * RR * HH)  // 131072 rows of W
#define NU 2048            // work units of 64 rows
#define NCTA 444           // persistent CTAs, 3 per SM
#define STAGES 4           // cp.async ring stages
#define STAGE_BYTES 8192   // 64 rows x 32 cols x 4B per stage

// Dynamic smem layout (bytes)
#define SM_W 0
#define SM_HS (STAGES * STAGE_BYTES)   // 32768: 8192 floats swizzled h_last
#define SM_SBLK (SM_HS + 32768)        // 256 floats: CTA-local S [h][r*8+b]
#define SM_SPTS (SM_SBLK + 1024)       // 16 ints: points
#define SM_MISC (SM_SPTS + 64)         // tickets + last flag
#define SMEM_TOTAL (SM_MISC + 64)

typedef unsigned long long ull;

// Scratch (device globals — no allocation allowed)
__device__ float g_S[256];       // [h][r*8+b] sums of exp (reset by last CTA each run)
__device__ float g_E[256];       // [b][h][r] selected-row exps (all slots rewritten every run)
__device__ unsigned g_tick = 0;  // work ticket counter (reset by last CTA)
__device__ unsigned g_fin = 0;   // finished-CTA counter (reset by last CTA)

__device__ __forceinline__ void fma2(ull& d, ull a, ull b) {
    asm("fma.rn.f32x2 %0, %1, %2, %0;" : "+l"(d) : "l"(a), "l"(b));
}
__device__ __forceinline__ ull packw(float f) {
    ull r;
    asm("mov.b64 %0, {%1, %1};" : "=l"(r) : "r"(__float_as_uint(f)));
    return r;
}
__device__ __forceinline__ float lo32(ull a) { return __uint_as_float((unsigned)a); }
__device__ __forceinline__ float hi32(ull a) { return __uint_as_float((unsigned)(a >> 32)); }

__device__ __forceinline__ void cp16(uint32_t dst, const float* src) {
    asm volatile("cp.async.cg.shared.global [%0], [%1], 16;" :: "r"(dst), "l"(src) : "memory");
}
__device__ __forceinline__ void cp_commit() {
    asm volatile("cp.async.commit_group;" ::: "memory");
}
__device__ __forceinline__ void cp_wait2() {
    asm volatile("cp.async.wait_group 2;" ::: "memory");
}
__device__ __forceinline__ void cp_waitall() {
    asm volatile("cp.async.wait_all;" ::: "memory");
}

// Reduce-scatter across the 8-lane c-group: on entry s[b] = lane-partial for batch b;
// on exit lane c holds the full (8-lane) sum for batch c. 7 shuffles.
__device__ __forceinline__ float rscatter8(const float s[8], int c) {
    bool b4 = (c & 4) != 0;
    float kp[4], snd[4];
#pragma unroll
    for (int i = 0; i < 4; i++) { snd[i] = b4 ? s[i] : s[i + 4]; kp[i] = b4 ? s[i + 4] : s[i]; }
#pragma unroll
    for (int i = 0; i < 4; i++) kp[i] += __shfl_xor_sync(0xffffffffu, snd[i], 4);
    bool b2 = (c & 2) != 0;
    float k2[2], s2[2];
#pragma unroll
    for (int i = 0; i < 2; i++) { s2[i] = b2 ? kp[i] : kp[i + 2]; k2[i] = b2 ? kp[i + 2] : kp[i]; }
#pragma unroll
    for (int i = 0; i < 2; i++) k2[i] += __shfl_xor_sync(0xffffffffu, s2[i], 2);
    bool b1 = (c & 1) != 0;
    float s1 = b1 ? k2[0] : k2[1];
    float k1 = b1 ? k2[1] : k2[0];
    return k1 + __shfl_xor_sync(0xffffffffu, s1, 1);
}

// Persistent kernel: 444 CTAs x 256 threads (3 CTAs/SM = 24 warps/SM). Each CTA
// pulls 64-row units via a global ticket. W flows through a 4-stage cp.async
// smem ring (8KB tiles, 3 groups = 24KB/CTA in flight, 72KB/SM). Each thread's
// cp.async chunks are exactly the chunks it later reads (self-consumer) ->
// wait_group alone synchronizes the ring; the only barriers are at unit
// boundaries, and the ring runs 3 tiles ahead so they never starve DRAM. The
// next unit's ticket is taken one unit early so prefetch crosses boundaries.
// h lives in smem, XOR-swizzled so the 8 c-groups broadcast (1 wavefront/LDS);
// the swizzle term for this layout reduces to a constant XOR with c.
__global__ void __launch_bounds__(256, 3) k_main(const float* __restrict__ lhs,
                                                 const float* __restrict__ Wm,
                                                 const float* __restrict__ bias,
                                                 const void* __restrict__ pts_raw,
                                                 float* __restrict__ out) {
    extern __shared__ char smem[];
    float* hs = (float*)(smem + SM_HS);
    float* sblk = (float*)(smem + SM_SBLK);
    int* spts = (int*)(smem + SM_SPTS);
    int* misc = (int*)(smem + SM_MISC);  // [0]=cur ticket, [1]=next ticket, [2]=last flag

    const int tid = threadIdx.x;
    const int warp = tid >> 5, lane = tid & 31;
    const int rgrp = lane >> 3, c = lane & 7;

    const uint32_t smem_u32 = (uint32_t)__cvta_generic_to_shared(smem);
    // This thread's private ring slot: + stage*8192 + q*512
    const uint32_t wbase = smem_u32 + SM_W + warp * 1024 + lane * 16;

    if (tid < 16) {
        // Detect int64 vs int32 points: values < 4096, so int64 data has all-zero hi words.
        const ull* pw = (const ull*)pts_raw;
        ull h = 0;
#pragma unroll
        for (int i = 0; i < 8; i++) h |= (pw[i] >> 32);
        bool is64 = (h == 0ULL);
        spts[tid] = is64 ? (int)((const long long*)pts_raw)[tid]
                         : ((const int*)pts_raw)[tid];
    }
    sblk[tid] = 0.f;

    // Stage h_last[b][k] = lhs[b, T-1, k] with XOR swizzle on 16B chunks.
#pragma unroll
    for (int i = 0; i < 32; i++) {
        int idx = tid + i * 256;
        int b = idx >> 10, k = idx & 1023;
        int idx16 = k * 2 + (b >> 2);
        int s = idx16 ^ ((idx16 >> 3) & 7);
        hs[s * 4 + (b & 3)] = lhs[b * (TT * DD) + (TT - 1) * DD + k];
    }

    if (tid == 0) {
        misc[0] = (int)atomicAdd(&g_tick, 1u);
        misc[1] = (int)atomicAdd(&g_tick, 1u);
    }
    __syncthreads();
    int cur = misc[0];
    int nxt = misc[1];

    const ulonglong2* h8 = (const ulonglong2*)hs;
    int swrite = STAGES - 1, sread = 0;

    // Prologue: issue tiles 0..STAGES-2 of cur
    if (cur < NU) {
        const float* g0 = Wm + (size_t)(cur * 64 + warp * 8 + rgrp) * 1024 + c * 4;
#pragma unroll
        for (int t = 0; t < STAGES - 1; t++) {
            uint32_t d = wbase + t * STAGE_BYTES;
            cp16(d, g0 + t * 32);
            cp16(d + 512, g0 + 4096 + t * 32);  // q=1: row +4
            cp_commit();
        }
    } else {
#pragma unroll
        for (int t = 0; t < STAGES - 1; t++) cp_commit();
    }

    while (cur < NU) {
        const float* gc = Wm + (size_t)(cur * 64 + warp * 8 + rgrp) * 1024 + c * 4;
        const float* gn = (nxt < NU)
                              ? Wm + (size_t)(nxt * 64 + warp * 8 + rgrp) * 1024 + c * 4
                              : (const float*)0;

        ull acc[2][4] = {};

        for (int t = 0; t < 32; t++) {
            cp_wait2();  // tile t complete (<= STAGES-2 groups pending)
            {
                int ft = t + (STAGES - 1);
                uint32_t d = wbase + swrite * STAGE_BYTES;
                if (ft < 32) {
                    cp16(d, gc + ft * 32);
                    cp16(d + 512, gc + 4096 + ft * 32);
                } else if (gn) {
                    int f2 = ft - 32;
                    cp16(d, gn + f2 * 32);
                    cp16(d + 512, gn + 4096 + f2 * 32);
                }
                cp_commit();  // always commit to keep group accounting uniform
                swrite++; if (swrite == STAGES) swrite = 0;
            }

            uint32_t s = wbase + sread * STAGE_BYTES;
            sread++; if (sread == STAGES) sread = 0;
            float4 w[2];
            asm volatile("ld.shared.v4.f32 {%0,%1,%2,%3}, [%4];"
                         : "=f"(w[0].x), "=f"(w[0].y), "=f"(w[0].z), "=f"(w[0].w)
                         : "r"(s));
            asm volatile("ld.shared.v4.f32 {%0,%1,%2,%3}, [%4];"
                         : "=f"(w[1].x), "=f"(w[1].y), "=f"(w[1].z), "=f"(w[1].w)
                         : "r"(s + 512));

            // h addresses: base has low-3 bits clear; swizzle reduces to XOR with c.
            const ulonglong2* hb = h8 + t * 64 + c * 8;
#define STEP(comp, kk)                                                        \
    do {                                                                      \
        ulonglong2 hA = hb[(2 * (kk)) ^ c];     /* batches 0-3 */             \
        ulonglong2 hB = hb[(2 * (kk) + 1) ^ c]; /* batches 4-7 */             \
        ull wd0 = packw(w[0].comp);                                           \
        fma2(acc[0][0], wd0, hA.x); fma2(acc[0][1], wd0, hA.y);               \
        fma2(acc[0][2], wd0, hB.x); fma2(acc[0][3], wd0, hB.y);               \
        ull wd1 = packw(w[1].comp);                                           \
        fma2(acc[1][0], wd1, hA.x); fma2(acc[1][1], wd1, hA.y);               \
        fma2(acc[1][2], wd1, hB.x); fma2(acc[1][3], wd1, hB.y);               \
    } while (0)
            STEP(x, 0);
            STEP(y, 1);
            STEP(z, 2);
            STEP(w, 3);
#undef STEP
        }

        // Unit epilogue: reduce-scatter (lane c ends with batch c), exp, accumulate.
        int hidx = cur >> 10;  // (cur*64) >> 16
#pragma unroll
        for (int q = 0; q < 2; q++) {
            float s[8];
#pragma unroll
            for (int p = 0; p < 4; p++) {
                s[2 * p] = lo32(acc[q][p]);
                s[2 * p + 1] = hi32(acc[q][p]);
            }
            float tot = rscatter8(s, c);
            int g = cur * 64 + warp * 8 + q * 4 + rgrp;
            float ev = expf(tot + __ldg(&bias[g]));
            int r = g & (RR - 1);
            atomicAdd(&sblk[hidx * 128 + r * 8 + c], ev);
            int v = (g >> 4) & (VV - 1);
            if (v == spts[c * 2 + hidx]) g_E[c * 32 + hidx * 16 + r] = ev;
        }

        // Advance: cur <- nxt (its early tiles are already in the ring), grab a new nxt.
        cur = nxt;
        if (cur < NU) {
            if (tid == 0) misc[1] = (int)atomicAdd(&g_tick, 1u);
            __syncthreads();
            nxt = misc[1];
        }
    }

    cp_waitall();    // drain ring before CTA teardown
    __syncthreads(); // all unit epilogues' sblk atomics done
    atomicAdd(&g_S[tid], sblk[tid]);  // tid in [0,256): one red per slot per CTA
    __threadfence();
    __syncthreads();
    if (tid == 0) {
        unsigned o = atomicAdd(&g_fin, 1u);
        misc[2] = (o == (unsigned)(NCTA - 1));
    }
    __syncthreads();

    if (misc[2]) {
        __threadfence();  // acquire: all CTAs' g_S reds visible
        if (tid < 8) {
            float n = 0.f, p = 0.f;
#pragma unroll
            for (int rr = 0; rr < 16; rr++) {
                n += g_S[rr * 8 + tid] * g_S[128 + rr * 8 + tid];
                p += g_E[tid * 32 + rr] * g_E[tid * 32 + 16 + rr];
            }
            out[tid] = p;       // p_eval
            out[8 + tid] = n;   // norm_const
        }
        __syncthreads();  // outputs written before scratch reset
        g_S[tid] = 0.f;   // reset for next graph replay
        if (tid == 0) { g_tick = 0; g_fin = 0; }
    }
}

extern "C" void kernel_launch(void* const* d_in, const int* in_sizes, int n_in,
                              void* d_out, int out_size) {
    // Identify inputs by element count (robust to ordering)
    const float* lhs = nullptr;
    const float* Wm = nullptr;
    const float* bias = nullptr;
    const void* pts = nullptr;
    for (int i = 0; i < n_in; i++) {
        int sz = in_sizes[i];
        if (sz == GG * DD) Wm = (const float*)d_in[i];
        else if (sz == BB * TT * DD) lhs = (const float*)d_in[i];
        else if (sz == GG) bias = (const float*)d_in[i];
        else if (sz == BB * HH) pts = d_in[i];
    }
    if (!lhs) lhs = (const float*)d_in[0];
    if (!Wm) Wm = (const float*)d_in[1];
    if (!bias) bias = (const float*)d_in[2];
    if (!pts) pts = d_in[3];

    cudaFuncSetAttribute(k_main, cudaFuncAttributeMaxDynamicSharedMemorySize, SMEM_TOTAL);
    k_main<<<NCTA, 256, SMEM_TOTAL>>>(lhs, Wm, bias, pts, (float*)d_out);
}